// round 13
// baseline (speedup 1.0000x reference)
#include <cuda_runtime.h>
#include <cuda_fp16.h>
#include <mma.h>

using namespace nvcuda;

// Problem constants (fixed by the dataset)
#define NN   50000
#define EE   800000
#define D1   128
#define HH   4
#define CC1  32
#define DOUT 32
#define SLOPE 0.2f
#define SMAX 128          // per-node bucket capacity (avg deg 16; overflow ~impossible)
#define NBLK_E4 ((EE / 4 + 255) / 256)   // 782 edge blocks in k_bucket
#define W2LD 48           // fp16 W2 row stride (96B = 6x16B, wmma-safe)

// ---------------- scratch (static device arrays: no allocation) -------------
__device__ int     g_deg[NN];        // zero at load; reset by k_agg2 each run
__device__ int     g_spad[NN * SMAX];// padded per-dst source buckets
__device__ __align__(16) __half2 g_xp1h[NN * 64];
__device__ __align__(16) __half  g_xp2h[NN * DOUT];
__device__ __align__(16) __half  g_w2h[128 * W2LD];  // W2 in fp16 (padded rows)
__device__ float   g_as1[NN * HH];
__device__ float   g_ad1[NN * HH];
__device__ float   g_as2[NN];
__device__ float   g_ad2[NN];

__device__ __forceinline__ float leaky(float v) { return v > 0.f ? v : SLOPE * v; }

// ---- fused rank+scatter + W2->fp16 conversion (tail blocks) ----------------
__global__ void k_bucket(const int* __restrict__ ei, const float* __restrict__ W2) {
    int b = blockIdx.x;
    if (b >= NBLK_E4) {
        // 4 tail blocks convert W2 (128x32 fp32 -> fp16, padded to W2LD)
        int idx = (b - NBLK_E4) * 256 + threadIdx.x;   // 0..1023 float4s
        if (idx < 1024) {
            int row = idx >> 3;
            int c4 = (idx & 7) * 4;
            float4 v = *(const float4*)(W2 + row * 32 + c4);
            __half* p = g_w2h + row * W2LD + c4;
            p[0] = __float2half_rn(v.x); p[1] = __float2half_rn(v.y);
            p[2] = __float2half_rn(v.z); p[3] = __float2half_rn(v.w);
        }
        return;
    }
    int e4 = b * blockDim.x + threadIdx.x;
    if (e4 < EE / 4) {
        int4 s = ((const int4*)ei)[e4];
        int4 d = ((const int4*)(ei + EE))[e4];
        int r;
        r = atomicAdd(&g_deg[d.x], 1); if (r < SMAX) g_spad[d.x * SMAX + r] = s.x;
        r = atomicAdd(&g_deg[d.y], 1); if (r < SMAX) g_spad[d.y * SMAX + r] = s.y;
        r = atomicAdd(&g_deg[d.z], 1); if (r < SMAX) g_spad[d.z * SMAX + r] = s.z;
        r = atomicAdd(&g_deg[d.w], 1); if (r < SMAX) g_spad[d.w * SMAX + r] = s.w;
    }
}

// ---- GEMM1 (tensor cores): xp1 = x @ W1, fp16 in / fp32 acc ---------------
#define GA_LD 136
#define GA_ABYTES (64 * GA_LD * 2)
#define GA_BBYTES (128 * GA_LD * 2)
#define GA_SMEM   (GA_ABYTES + GA_BBYTES)
#define GC_LD 132

__global__ void __launch_bounds__(256)
k_gemm1(const float* __restrict__ x, const float* __restrict__ W,
        const float* __restrict__ asrc, const float* __restrict__ adst) {
    extern __shared__ char smem_raw[];
    __half* Ah = (__half*)smem_raw;
    __half* Bh = (__half*)(smem_raw + GA_ABYTES);
    float*  Cf = (float*)smem_raw;               // reused after mainloop

    int t = threadIdx.x;
    int lane = t & 31;
    int warp = t >> 5;
    int row0 = blockIdx.x * 64;
    int wm = warp >> 2;
    int wn = warp & 3;

    #pragma unroll
    for (int i = 0; i < 8; i++) {
        int idx = t + i * 256;
        int row = idx >> 5;
        int c4 = (idx & 31) * 4;
        int grow = row0 + row;
        float4 v = (grow < NN) ? *(const float4*)(x + grow * 128 + c4)
                               : make_float4(0, 0, 0, 0);
        __half* p = Ah + row * GA_LD + c4;
        p[0] = __float2half_rn(v.x); p[1] = __float2half_rn(v.y);
        p[2] = __float2half_rn(v.z); p[3] = __float2half_rn(v.w);
    }
    #pragma unroll
    for (int i = 0; i < 16; i++) {
        int idx = t + i * 256;
        int row = idx >> 5;
        int c4 = (idx & 31) * 4;
        float4 v = *(const float4*)(W + row * 128 + c4);
        __half* p = Bh + row * GA_LD + c4;
        p[0] = __float2half_rn(v.x); p[1] = __float2half_rn(v.y);
        p[2] = __float2half_rn(v.z); p[3] = __float2half_rn(v.w);
    }
    __syncthreads();

    wmma::fragment<wmma::accumulator, 16, 16, 16, float> c[2][2];
    #pragma unroll
    for (int i = 0; i < 2; i++)
        #pragma unroll
        for (int j = 0; j < 2; j++)
            wmma::fill_fragment(c[i][j], 0.0f);

    #pragma unroll
    for (int k0 = 0; k0 < 128; k0 += 16) {
        wmma::fragment<wmma::matrix_a, 16, 16, 16, __half, wmma::row_major> a[2];
        wmma::fragment<wmma::matrix_b, 16, 16, 16, __half, wmma::row_major> b[2];
        #pragma unroll
        for (int i = 0; i < 2; i++)
            wmma::load_matrix_sync(a[i], Ah + (wm * 32 + i * 16) * GA_LD + k0, GA_LD);
        #pragma unroll
        for (int j = 0; j < 2; j++)
            wmma::load_matrix_sync(b[j], Bh + k0 * GA_LD + wn * 32 + j * 16, GA_LD);
        #pragma unroll
        for (int i = 0; i < 2; i++)
            #pragma unroll
            for (int j = 0; j < 2; j++)
                wmma::mma_sync(c[i][j], a[i], b[j], c[i][j]);
    }
    __syncthreads();

    #pragma unroll
    for (int i = 0; i < 2; i++)
        #pragma unroll
        for (int j = 0; j < 2; j++)
            wmma::store_matrix_sync(Cf + (wm * 32 + i * 16) * GC_LD + wn * 32 + j * 16,
                                    c[i][j], GC_LD, wmma::mem_row_major);
    __syncthreads();

    int c0 = lane * 4;
    float4 asv = *(const float4*)(asrc + c0);
    float4 adv = *(const float4*)(adst + c0);
    int h = lane >> 3;
    #pragma unroll
    for (int rr = 0; rr < 8; rr++) {
        int row = warp * 8 + rr;
        int grow = row0 + row;
        float4 v = *(const float4*)(Cf + row * GC_LD + c0);
        if (grow < NN) {
            __half2 h0 = __floats2half2_rn(v.x, v.y);
            __half2 h1 = __floats2half2_rn(v.z, v.w);
            uint2 pk;
            pk.x = *(unsigned*)&h0;
            pk.y = *(unsigned*)&h1;
            *(uint2*)(g_xp1h + grow * 64 + lane * 2) = pk;
        }
        float ps = v.x * asv.x + v.y * asv.y + v.z * asv.z + v.w * asv.w;
        float pd = v.x * adv.x + v.y * adv.y + v.z * adv.z + v.w * adv.w;
        #pragma unroll
        for (int o = 1; o < 8; o <<= 1) {
            ps += __shfl_xor_sync(0xffffffffu, ps, o);
            pd += __shfl_xor_sync(0xffffffffu, pd, o);
        }
        if ((lane & 7) == 0 && grow < NN) {
            g_as1[grow * 4 + h] = ps;
            g_ad1[grow * 4 + h] = pd;
        }
    }
}

// ---- fused layer-1 aggregation + layer-2 GEMM + layer-2 attention dots -----
// 512 threads = 16 warps = 16 nodes per block; 3125 blocks = 50000 exactly.
#define HS_LD 136
#define CF_LD 36

__global__ void __launch_bounds__(512)
k_agg1f(const float* __restrict__ b1,
        const float* __restrict__ as2v, const float* __restrict__ ad2v) {
    __shared__ __half Hs[16 * HS_LD];    // 16 nodes x 128 ch (fp16)
    __shared__ float  Cs[16 * CF_LD];    // xp2 tile (fp32)

    int t = threadIdx.x;
    int warp = t >> 5;
    int lane = t & 31;
    int i = blockIdx.x * 16 + warp;      // node (always < NN)

    int deg = g_deg[i]; if (deg > SMAX) deg = SMAX;
    const int* ebase = g_spad + i * SMAX;
    int myhead = lane >> 3;          // weight-compute role: head
    int es = lane & 7;               // weight-compute role: edge slot
    int h4 = lane >> 4;              // gather role: edge parity
    int lane15 = lane & 15;          // gather role: channel group (8 ch)
    int wbase = (lane & 12) << 1;    // lane base holding my gather-head's weights
    float adh = g_ad1[i * 4 + myhead];

    // self contribution (implicit self loop)
    float denl = (es == 0) ? __expf(leaky(g_as1[i * 4 + myhead] + adh)) : 0.f;
    float acc[8];
    #pragma unroll
    for (int k = 0; k < 8; k++) acc[k] = 0.f;
    if (h4 == 0) {
        int hh2 = lane15 >> 2;       // head covering my channel group
        float wself = __expf(leaky(g_as1[i * 4 + hh2] + g_ad1[i * 4 + hh2]));
        uint4 p = *(const uint4*)(g_xp1h + i * 64 + lane15 * 4);
        float2 v0 = __half22float2(*(__half2*)&p.x);
        float2 v1 = __half22float2(*(__half2*)&p.y);
        float2 v2 = __half22float2(*(__half2*)&p.z);
        float2 v3 = __half22float2(*(__half2*)&p.w);
        acc[0] = wself * v0.x; acc[1] = wself * v0.y;
        acc[2] = wself * v1.x; acc[3] = wself * v1.y;
        acc[4] = wself * v2.x; acc[5] = wself * v2.y;
        acc[6] = wself * v3.x; acc[7] = wself * v3.y;
    }

    for (int base = 0; base < deg; base += 8) {
        int n = deg - base; if (n > 8) n = 8;
        int src_l = i;
        float w_l = 0.f;
        if (es < n) {
            src_l = ebase[base + es];
            w_l = __expf(leaky(g_as1[src_l * 4 + myhead] + adh));
        }
        denl += w_l;
        int npair = (n + 1) >> 1;
        for (int j = 0; j < npair; j++) {
            int slot = 2 * j + h4;
            int src = __shfl_sync(0xffffffffu, src_l, slot);
            float wv = __shfl_sync(0xffffffffu, w_l, wbase + slot);
            if (slot < n) {
                uint4 p = *(const uint4*)(g_xp1h + src * 64 + lane15 * 4);
                float2 v0 = __half22float2(*(__half2*)&p.x);
                float2 v1 = __half22float2(*(__half2*)&p.y);
                float2 v2 = __half22float2(*(__half2*)&p.z);
                float2 v3 = __half22float2(*(__half2*)&p.w);
                acc[0] = fmaf(wv, v0.x, acc[0]); acc[1] = fmaf(wv, v0.y, acc[1]);
                acc[2] = fmaf(wv, v1.x, acc[2]); acc[3] = fmaf(wv, v1.y, acc[3]);
                acc[4] = fmaf(wv, v2.x, acc[4]); acc[5] = fmaf(wv, v2.y, acc[5]);
                acc[6] = fmaf(wv, v3.x, acc[6]); acc[7] = fmaf(wv, v3.y, acc[7]);
            }
        }
    }
    // per-head denominators (8-lane groups), broadcast to gather lanes
    denl += __shfl_xor_sync(0xffffffffu, denl, 1);
    denl += __shfl_xor_sync(0xffffffffu, denl, 2);
    denl += __shfl_xor_sync(0xffffffffu, denl, 4);
    float denv = __shfl_sync(0xffffffffu, denl, wbase);
    float inv = 1.0f / denv;
    // combine the two edge-parity halves
    #pragma unroll
    for (int k = 0; k < 8; k++)
        acc[k] += __shfl_xor_sync(0xffffffffu, acc[k], 16);
    // bias + relu + fp16 store to the block's Hs tile
    int ch0 = lane15 * 8;
    float4 bb0 = *(const float4*)(b1 + ch0);
    float4 bb1 = *(const float4*)(b1 + ch0 + 4);
    __half hv[8];
    hv[0] = __float2half_rn(fmaxf(fmaf(acc[0], inv, bb0.x), 0.f));
    hv[1] = __float2half_rn(fmaxf(fmaf(acc[1], inv, bb0.y), 0.f));
    hv[2] = __float2half_rn(fmaxf(fmaf(acc[2], inv, bb0.z), 0.f));
    hv[3] = __float2half_rn(fmaxf(fmaf(acc[3], inv, bb0.w), 0.f));
    hv[4] = __float2half_rn(fmaxf(fmaf(acc[4], inv, bb1.x), 0.f));
    hv[5] = __float2half_rn(fmaxf(fmaf(acc[5], inv, bb1.y), 0.f));
    hv[6] = __float2half_rn(fmaxf(fmaf(acc[6], inv, bb1.z), 0.f));
    hv[7] = __float2half_rn(fmaxf(fmaf(acc[7], inv, bb1.w), 0.f));
    if (h4 == 0)
        *(uint4*)(&Hs[warp * HS_LD + ch0]) = *(uint4*)hv;
    __syncthreads();

    // layer-2 GEMM on the 16x128 tile: warps 0/1 each do a 16-col half
    if (warp < 2) {
        wmma::fragment<wmma::accumulator, 16, 16, 16, float> c;
        wmma::fill_fragment(c, 0.0f);
        #pragma unroll
        for (int k0 = 0; k0 < 128; k0 += 16) {
            wmma::fragment<wmma::matrix_a, 16, 16, 16, __half, wmma::row_major> a;
            wmma::fragment<wmma::matrix_b, 16, 16, 16, __half, wmma::row_major> b;
            wmma::load_matrix_sync(a, Hs + k0, HS_LD);
            wmma::load_matrix_sync(b, g_w2h + k0 * W2LD + warp * 16, W2LD);
            wmma::mma_sync(c, a, b, c);
        }
        wmma::store_matrix_sync(Cs + warp * 16, c, CF_LD, wmma::mem_row_major);
    }
    __syncthreads();

    // epilogue: warp per node row; lane covers one of 32 cols
    float v = Cs[warp * CF_LD + lane];
    float ps = v * as2v[lane];
    float pd = v * ad2v[lane];
    #pragma unroll
    for (int o = 1; o < 32; o <<= 1) {
        ps += __shfl_xor_sync(0xffffffffu, ps, o);
        pd += __shfl_xor_sync(0xffffffffu, pd, o);
    }
    if (lane == 0) { g_as2[i] = ps; g_ad2[i] = pd; }
    float vodd = __shfl_xor_sync(0xffffffffu, v, 1);
    if ((lane & 1) == 0) {
        __half2 pk = __floats2half2_rn(v, vodd);
        *(__half2*)(g_xp2h + i * 32 + lane) = pk;
    }
}

// ---- layer-2 aggregation: warp/node, implicit self, bucket reads, deg reset
__global__ void __launch_bounds__(256)
k_agg2(const float* __restrict__ b2, float* __restrict__ out) {
    int gw = (blockIdx.x * blockDim.x + threadIdx.x) >> 5;
    int lane = threadIdx.x & 31;
    if (gw >= NN) return;
    int i = gw;
    int deg = g_deg[i]; if (deg > SMAX) deg = SMAX;
    const int* ebase = g_spad + i * SMAX;
    float ad = g_ad2[i];
    int q4 = lane >> 2;       // gather role: edge sub-slot 0..7
    int cg = lane & 3;        // gather role: channel group (8 halves)

    // self contribution (implicit self loop)
    float wself = __expf(leaky(g_as2[i] + ad));
    float den = (lane == 0) ? wself : 0.f;
    float acc[8];
    #pragma unroll
    for (int k = 0; k < 8; k++) acc[k] = 0.f;
    if (q4 == 0) {
        uint4 p = *(const uint4*)(g_xp2h + i * 32 + cg * 8);
        float2 v0 = __half22float2(*(__half2*)&p.x);
        float2 v1 = __half22float2(*(__half2*)&p.y);
        float2 v2 = __half22float2(*(__half2*)&p.z);
        float2 v3 = __half22float2(*(__half2*)&p.w);
        acc[0] = wself * v0.x; acc[1] = wself * v0.y;
        acc[2] = wself * v1.x; acc[3] = wself * v1.y;
        acc[4] = wself * v2.x; acc[5] = wself * v2.y;
        acc[6] = wself * v3.x; acc[7] = wself * v3.y;
    }

    for (int base = 0; base < deg; base += 32) {
        int n = deg - base; if (n > 32) n = 32;
        int src_l = i;
        float w_l = 0.f;
        if (lane < n) {
            src_l = ebase[base + lane];
            w_l = __expf(leaky(g_as2[src_l] + ad));
        }
        den += w_l;
        int niter = (n + 7) >> 3;
        for (int j = 0; j < niter; j++) {
            int slot = 8 * j + q4;
            int src = __shfl_sync(0xffffffffu, src_l, slot);
            float wv = __shfl_sync(0xffffffffu, w_l, slot);
            if (slot < n) {
                uint4 p = *(const uint4*)(g_xp2h + src * 32 + cg * 8);
                float2 v0 = __half22float2(*(__half2*)&p.x);
                float2 v1 = __half22float2(*(__half2*)&p.y);
                float2 v2 = __half22float2(*(__half2*)&p.z);
                float2 v3 = __half22float2(*(__half2*)&p.w);
                acc[0] = fmaf(wv, v0.x, acc[0]); acc[1] = fmaf(wv, v0.y, acc[1]);
                acc[2] = fmaf(wv, v1.x, acc[2]); acc[3] = fmaf(wv, v1.y, acc[3]);
                acc[4] = fmaf(wv, v2.x, acc[4]); acc[5] = fmaf(wv, v2.y, acc[5]);
                acc[6] = fmaf(wv, v3.x, acc[6]); acc[7] = fmaf(wv, v3.y, acc[7]);
            }
        }
    }
    // reset degree for the next replay (deterministic rebuild)
    if (lane == 0) g_deg[i] = 0;

    #pragma unroll
    for (int o = 16; o; o >>= 1)
        den += __shfl_xor_sync(0xffffffffu, den, o);
    #pragma unroll
    for (int k = 0; k < 8; k++) {
        acc[k] += __shfl_xor_sync(0xffffffffu, acc[k], 4);
        acc[k] += __shfl_xor_sync(0xffffffffu, acc[k], 8);
        acc[k] += __shfl_xor_sync(0xffffffffu, acc[k], 16);
    }
    float inv = 1.0f / den;
    if (lane < 4) {
        int ch0 = cg * 8;
        float4 o0, o1;
        o0.x = fmaf(acc[0], inv, b2[ch0 + 0]);
        o0.y = fmaf(acc[1], inv, b2[ch0 + 1]);
        o0.z = fmaf(acc[2], inv, b2[ch0 + 2]);
        o0.w = fmaf(acc[3], inv, b2[ch0 + 3]);
        o1.x = fmaf(acc[4], inv, b2[ch0 + 4]);
        o1.y = fmaf(acc[5], inv, b2[ch0 + 5]);
        o1.z = fmaf(acc[6], inv, b2[ch0 + 6]);
        o1.w = fmaf(acc[7], inv, b2[ch0 + 7]);
        *(float4*)(out + i * 32 + ch0)     = o0;
        *(float4*)(out + i * 32 + ch0 + 4) = o1;
    }
}

// ---------------- launch ----------------------------------------------------
extern "C" void kernel_launch(void* const* d_in, const int* in_sizes, int n_in,
                              void* d_out, int out_size) {
    const float* x   = (const float*)d_in[0];
    const int*   ei  = (const int*)  d_in[1];
    const float* W1  = (const float*)d_in[2];
    const float* as1 = (const float*)d_in[3];
    const float* ad1 = (const float*)d_in[4];
    const float* b1  = (const float*)d_in[5];
    const float* W2  = (const float*)d_in[6];
    const float* as2 = (const float*)d_in[7];
    const float* ad2 = (const float*)d_in[8];
    const float* b2  = (const float*)d_in[9];
    float* out = (float*)d_out;

    const int nblkW = (NN * 32 + 255) / 256;   // one warp per node (agg2)

    static bool init_done = false;
    static cudaStream_t s2 = 0;
    static cudaEvent_t evF = 0, evJ = 0;
    if (!init_done) {
        cudaFuncSetAttribute(k_gemm1, cudaFuncAttributeMaxDynamicSharedMemorySize,
                             GA_SMEM);
        cudaStream_t st;
        if (cudaStreamCreateWithFlags(&st, cudaStreamNonBlocking) == cudaSuccess &&
            cudaEventCreateWithFlags(&evF, cudaEventDisableTiming) == cudaSuccess &&
            cudaEventCreateWithFlags(&evJ, cudaEventDisableTiming) == cudaSuccess) {
            s2 = st;
        } else {
            s2 = 0;
        }
        init_done = true;
    }

    // fork GEMM1 (independent of adjacency build) onto second stream
    if (s2) {
        cudaEventRecord(evF, 0);
        cudaStreamWaitEvent(s2, evF, 0);
        k_gemm1<<<(NN + 63) / 64, 256, GA_SMEM, s2>>>(x, W1, as1, ad1);
        cudaEventRecord(evJ, s2);
    }

    // adjacency build + W2 fp16 conversion: single fused kernel
    k_bucket<<<NBLK_E4 + 4, 256>>>(ei, W2);

    if (s2) {
        cudaStreamWaitEvent(0, evJ, 0);
    } else {
        k_gemm1<<<(NN + 63) / 64, 256, GA_SMEM>>>(x, W1, as1, ad1);
    }

    // fused agg1 + layer-2 GEMM + layer-2 dots (16 nodes per 512-thread block)
    k_agg1f<<<NN / 16, 512>>>(b1, as2, ad2);
    k_agg2<<<nblkW, 256>>>(b2, out);
}

// round 14
// speedup vs baseline: 1.4361x; 1.4361x over previous
#include <cuda_runtime.h>
#include <cuda_fp16.h>
#include <mma.h>

using namespace nvcuda;

// Problem constants (fixed by the dataset)
#define NN   50000
#define EE   800000
#define D1   128
#define HH   4
#define CC1  32
#define DOUT 32
#define SLOPE 0.2f
#define SMAX 128          // per-node bucket capacity (avg deg 16; overflow ~impossible)

// ---------------- scratch (static device arrays: no allocation) -------------
__device__ int     g_deg[NN];        // zero at load; reset by k_agg2 each run
__device__ int     g_spad[NN * SMAX];// padded per-dst source buckets
__device__ __align__(16) __half2 g_xp1h[NN * 64];
__device__ __align__(16) __half  g_hh[NN * D1];
__device__ __align__(16) float   g_xp2f[NN * DOUT];   // xp2 in fp32
__device__ float   g_as1[NN * HH];
__device__ float   g_ad1[NN * HH];
__device__ float   g_as2[NN];
__device__ float   g_ad2[NN];

__device__ __forceinline__ float leaky(float v) { return v > 0.f ? v : SLOPE * v; }

// packed fp32x2 FMA (Blackwell): d += a*b elementwise on 2 floats
__device__ __forceinline__ void fma2(unsigned long long& d, unsigned long long a,
                                     unsigned long long b) {
    asm("fma.rn.f32x2 %0, %1, %2, %0;" : "+l"(d) : "l"(a), "l"(b));
}
__device__ __forceinline__ unsigned long long pack2(float x) {
    unsigned long long r;
    asm("mov.b64 %0, {%1, %1};" : "=l"(r) : "f"(x));
    return r;
}
__device__ __forceinline__ unsigned long long packf2(float2 v) {
    unsigned long long r;
    asm("mov.b64 %0, {%1, %2};" : "=l"(r) : "f"(v.x), "f"(v.y));
    return r;
}
__device__ __forceinline__ float2 unpk2(unsigned long long v) {
    float2 r;
    asm("mov.b64 {%0, %1}, %2;" : "=f"(r.x), "=f"(r.y) : "l"(v));
    return r;
}

// ---- fused rank+scatter: ONE kernel builds the whole adjacency -------------
__global__ void k_bucket(const int* __restrict__ ei) {
    int e4 = blockIdx.x * blockDim.x + threadIdx.x;
    if (e4 < EE / 4) {
        int4 s = ((const int4*)ei)[e4];
        int4 d = ((const int4*)(ei + EE))[e4];
        int r;
        r = atomicAdd(&g_deg[d.x], 1); if (r < SMAX) g_spad[d.x * SMAX + r] = s.x;
        r = atomicAdd(&g_deg[d.y], 1); if (r < SMAX) g_spad[d.y * SMAX + r] = s.y;
        r = atomicAdd(&g_deg[d.z], 1); if (r < SMAX) g_spad[d.z * SMAX + r] = s.z;
        r = atomicAdd(&g_deg[d.w], 1); if (r < SMAX) g_spad[d.w * SMAX + r] = s.w;
    }
}

// ---- GEMM1 (tensor cores): xp1 = x @ W1, fp16 in / fp32 acc ---------------
#define GA_LD 136
#define GA_ABYTES (64 * GA_LD * 2)
#define GA_BBYTES (128 * GA_LD * 2)
#define GA_SMEM   (GA_ABYTES + GA_BBYTES)
#define GC_LD 132

__global__ void __launch_bounds__(256)
k_gemm1(const float* __restrict__ x, const float* __restrict__ W,
        const float* __restrict__ asrc, const float* __restrict__ adst) {
    extern __shared__ char smem_raw[];
    __half* Ah = (__half*)smem_raw;
    __half* Bh = (__half*)(smem_raw + GA_ABYTES);
    float*  Cf = (float*)smem_raw;               // reused after mainloop

    int t = threadIdx.x;
    int lane = t & 31;
    int warp = t >> 5;
    int row0 = blockIdx.x * 64;
    int wm = warp >> 2;
    int wn = warp & 3;

    #pragma unroll
    for (int i = 0; i < 8; i++) {
        int idx = t + i * 256;
        int row = idx >> 5;
        int c4 = (idx & 31) * 4;
        int grow = row0 + row;
        float4 v = (grow < NN) ? *(const float4*)(x + grow * 128 + c4)
                               : make_float4(0, 0, 0, 0);
        __half* p = Ah + row * GA_LD + c4;
        p[0] = __float2half_rn(v.x); p[1] = __float2half_rn(v.y);
        p[2] = __float2half_rn(v.z); p[3] = __float2half_rn(v.w);
    }
    #pragma unroll
    for (int i = 0; i < 16; i++) {
        int idx = t + i * 256;
        int row = idx >> 5;
        int c4 = (idx & 31) * 4;
        float4 v = *(const float4*)(W + row * 128 + c4);
        __half* p = Bh + row * GA_LD + c4;
        p[0] = __float2half_rn(v.x); p[1] = __float2half_rn(v.y);
        p[2] = __float2half_rn(v.z); p[3] = __float2half_rn(v.w);
    }
    __syncthreads();

    wmma::fragment<wmma::accumulator, 16, 16, 16, float> c[2][2];
    #pragma unroll
    for (int i = 0; i < 2; i++)
        #pragma unroll
        for (int j = 0; j < 2; j++)
            wmma::fill_fragment(c[i][j], 0.0f);

    #pragma unroll
    for (int k0 = 0; k0 < 128; k0 += 16) {
        wmma::fragment<wmma::matrix_a, 16, 16, 16, __half, wmma::row_major> a[2];
        wmma::fragment<wmma::matrix_b, 16, 16, 16, __half, wmma::row_major> b[2];
        #pragma unroll
        for (int i = 0; i < 2; i++)
            wmma::load_matrix_sync(a[i], Ah + (wm * 32 + i * 16) * GA_LD + k0, GA_LD);
        #pragma unroll
        for (int j = 0; j < 2; j++)
            wmma::load_matrix_sync(b[j], Bh + k0 * GA_LD + wn * 32 + j * 16, GA_LD);
        #pragma unroll
        for (int i = 0; i < 2; i++)
            #pragma unroll
            for (int j = 0; j < 2; j++)
                wmma::mma_sync(c[i][j], a[i], b[j], c[i][j]);
    }
    __syncthreads();

    #pragma unroll
    for (int i = 0; i < 2; i++)
        #pragma unroll
        for (int j = 0; j < 2; j++)
            wmma::store_matrix_sync(Cf + (wm * 32 + i * 16) * GC_LD + wn * 32 + j * 16,
                                    c[i][j], GC_LD, wmma::mem_row_major);
    __syncthreads();

    int c0 = lane * 4;
    float4 asv = *(const float4*)(asrc + c0);
    float4 adv = *(const float4*)(adst + c0);
    int h = lane >> 3;
    #pragma unroll
    for (int rr = 0; rr < 8; rr++) {
        int row = warp * 8 + rr;
        int grow = row0 + row;
        float4 v = *(const float4*)(Cf + row * GC_LD + c0);
        if (grow < NN) {
            __half2 h0 = __floats2half2_rn(v.x, v.y);
            __half2 h1 = __floats2half2_rn(v.z, v.w);
            uint2 pk;
            pk.x = *(unsigned*)&h0;
            pk.y = *(unsigned*)&h1;
            *(uint2*)(g_xp1h + grow * 64 + lane * 2) = pk;
        }
        float ps = v.x * asv.x + v.y * asv.y + v.z * asv.z + v.w * asv.w;
        float pd = v.x * adv.x + v.y * adv.y + v.z * adv.z + v.w * adv.w;
        #pragma unroll
        for (int o = 1; o < 8; o <<= 1) {
            ps += __shfl_xor_sync(0xffffffffu, ps, o);
            pd += __shfl_xor_sync(0xffffffffu, pd, o);
        }
        if ((lane & 7) == 0 && grow < NN) {
            g_as1[grow * 4 + h] = ps;
            g_ad1[grow * 4 + h] = pd;
        }
    }
}

// ---- layer-1 aggregation: warp/node, fp16 gathers, packed FFMA2 ------------
__global__ void __launch_bounds__(256) k_agg1(const float* __restrict__ b1) {
    int gw = (blockIdx.x * blockDim.x + threadIdx.x) >> 5;
    int lane = threadIdx.x & 31;
    if (gw >= NN) return;
    int i = gw;
    int deg = g_deg[i]; if (deg > SMAX) deg = SMAX;
    const int* ebase = g_spad + i * SMAX;
    int myhead = lane >> 3;          // weight-compute role: head
    int es = lane & 7;               // weight-compute role: edge slot
    int h4 = lane >> 4;              // gather role: edge parity
    int lane15 = lane & 15;          // gather role: channel group (8 ch)
    int wbase = (lane & 12) << 1;    // lane base holding my gather-head's weights
    float adh = g_ad1[i * 4 + myhead];

    // self contribution (implicit self loop)
    float denl = (es == 0) ? __expf(leaky(g_as1[i * 4 + myhead] + adh)) : 0.f;
    unsigned long long acc2[4] = {0ull, 0ull, 0ull, 0ull};
    if (h4 == 0) {
        int hh2 = lane15 >> 2;       // head covering my channel group
        float wself = __expf(leaky(g_as1[i * 4 + hh2] + g_ad1[i * 4 + hh2]));
        unsigned long long wp = pack2(wself);
        uint4 p = *(const uint4*)(g_xp1h + i * 64 + lane15 * 4);
        fma2(acc2[0], wp, packf2(__half22float2(*(__half2*)&p.x)));
        fma2(acc2[1], wp, packf2(__half22float2(*(__half2*)&p.y)));
        fma2(acc2[2], wp, packf2(__half22float2(*(__half2*)&p.z)));
        fma2(acc2[3], wp, packf2(__half22float2(*(__half2*)&p.w)));
    }

    for (int base = 0; base < deg; base += 8) {
        int n = deg - base; if (n > 8) n = 8;
        int src_l = i;
        float w_l = 0.f;
        if (es < n) {
            src_l = ebase[base + es];
            w_l = __expf(leaky(g_as1[src_l * 4 + myhead] + adh));
        }
        denl += w_l;
        int npair = (n + 1) >> 1;
        for (int j = 0; j < npair; j++) {
            int slot = 2 * j + h4;
            int src = __shfl_sync(0xffffffffu, src_l, slot);
            float wv = __shfl_sync(0xffffffffu, w_l, wbase + slot);
            if (slot < n) {
                unsigned long long wp = pack2(wv);
                uint4 p = *(const uint4*)(g_xp1h + src * 64 + lane15 * 4);
                fma2(acc2[0], wp, packf2(__half22float2(*(__half2*)&p.x)));
                fma2(acc2[1], wp, packf2(__half22float2(*(__half2*)&p.y)));
                fma2(acc2[2], wp, packf2(__half22float2(*(__half2*)&p.z)));
                fma2(acc2[3], wp, packf2(__half22float2(*(__half2*)&p.w)));
            }
        }
    }
    // per-head denominators (8-lane groups), broadcast to gather lanes
    denl += __shfl_xor_sync(0xffffffffu, denl, 1);
    denl += __shfl_xor_sync(0xffffffffu, denl, 2);
    denl += __shfl_xor_sync(0xffffffffu, denl, 4);
    float denv = __shfl_sync(0xffffffffu, denl, wbase);
    float inv = 1.0f / denv;
    // unpack + combine the two edge-parity halves
    float acc[8];
    #pragma unroll
    for (int k = 0; k < 4; k++) {
        float2 u = unpk2(acc2[k]);
        acc[2 * k] = u.x; acc[2 * k + 1] = u.y;
    }
    #pragma unroll
    for (int k = 0; k < 8; k++)
        acc[k] += __shfl_xor_sync(0xffffffffu, acc[k], 16);
    // bias + relu + fp16 store (lanes 0-15 cover all 128 channels)
    int ch0 = lane15 * 8;
    float4 bb0 = *(const float4*)(b1 + ch0);
    float4 bb1 = *(const float4*)(b1 + ch0 + 4);
    __half hv[8];
    hv[0] = __float2half_rn(fmaxf(fmaf(acc[0], inv, bb0.x), 0.f));
    hv[1] = __float2half_rn(fmaxf(fmaf(acc[1], inv, bb0.y), 0.f));
    hv[2] = __float2half_rn(fmaxf(fmaf(acc[2], inv, bb0.z), 0.f));
    hv[3] = __float2half_rn(fmaxf(fmaf(acc[3], inv, bb0.w), 0.f));
    hv[4] = __float2half_rn(fmaxf(fmaf(acc[4], inv, bb1.x), 0.f));
    hv[5] = __float2half_rn(fmaxf(fmaf(acc[5], inv, bb1.y), 0.f));
    hv[6] = __float2half_rn(fmaxf(fmaf(acc[6], inv, bb1.z), 0.f));
    hv[7] = __float2half_rn(fmaxf(fmaf(acc[7], inv, bb1.w), 0.f));
    if (h4 == 0)
        *(uint4*)(g_hh + i * 128 + ch0) = *(uint4*)hv;
}

// ---- GEMM2 (tensor cores): xp2 = h @ W2 (fp32 out) + fused attention dots --
#define G2_ALD 136
#define G2_BLD 40
#define G2_CLD 36

__global__ void __launch_bounds__(256)
k_gemm2(const float* __restrict__ W2,
        const float* __restrict__ asrc, const float* __restrict__ adst) {
    __shared__ __half Ah[128 * G2_ALD];
    __shared__ __half Bh[128 * G2_BLD];
    float* Cf = (float*)Ah;

    int t = threadIdx.x;
    int warp = t >> 5;
    int row0 = blockIdx.x * 128;

    #pragma unroll
    for (int i = 0; i < 8; i++) {
        int idx = t + i * 256;
        int row = idx >> 4;
        int q = idx & 15;
        int grow = row0 + row;
        uint4 v = (grow < NN) ? *(const uint4*)(g_hh + grow * 128 + q * 8)
                              : make_uint4(0, 0, 0, 0);
        *(uint4*)(Ah + row * G2_ALD + q * 8) = v;
    }
    #pragma unroll
    for (int i = 0; i < 4; i++) {
        int idx = t + i * 256;
        int row = idx >> 3;
        int c4 = (idx & 7) * 4;
        float4 v = *(const float4*)(W2 + row * 32 + c4);
        __half* p = Bh + row * G2_BLD + c4;
        p[0] = __float2half_rn(v.x); p[1] = __float2half_rn(v.y);
        p[2] = __float2half_rn(v.z); p[3] = __float2half_rn(v.w);
    }
    __syncthreads();

    wmma::fragment<wmma::accumulator, 16, 16, 16, float> c[2];
    wmma::fill_fragment(c[0], 0.0f);
    wmma::fill_fragment(c[1], 0.0f);

    #pragma unroll
    for (int k0 = 0; k0 < 128; k0 += 16) {
        wmma::fragment<wmma::matrix_a, 16, 16, 16, __half, wmma::row_major> a;
        wmma::fragment<wmma::matrix_b, 16, 16, 16, __half, wmma::row_major> b[2];
        wmma::load_matrix_sync(a, Ah + (warp * 16) * G2_ALD + k0, G2_ALD);
        wmma::load_matrix_sync(b[0], Bh + k0 * G2_BLD + 0, G2_BLD);
        wmma::load_matrix_sync(b[1], Bh + k0 * G2_BLD + 16, G2_BLD);
        wmma::mma_sync(c[0], a, b[0], c[0]);
        wmma::mma_sync(c[1], a, b[1], c[1]);
    }
    __syncthreads();

    wmma::store_matrix_sync(Cf + (warp * 16) * G2_CLD + 0,  c[0], G2_CLD,
                            wmma::mem_row_major);
    wmma::store_matrix_sync(Cf + (warp * 16) * G2_CLD + 16, c[1], G2_CLD,
                            wmma::mem_row_major);
    __syncthreads();

    int row = t >> 1;
    int c0 = (t & 1) * 16;
    int grow = row0 + row;
    float v[16];
    #pragma unroll
    for (int j = 0; j < 16; j++) v[j] = Cf[row * G2_CLD + c0 + j];

    float ps = 0.f, pd = 0.f;
    #pragma unroll
    for (int j = 0; j < 16; j++) {
        ps = fmaf(v[j], asrc[c0 + j], ps);
        pd = fmaf(v[j], adst[c0 + j], pd);
    }
    ps += __shfl_xor_sync(0xffffffffu, ps, 1);
    pd += __shfl_xor_sync(0xffffffffu, pd, 1);

    if (grow < NN) {
        #pragma unroll
        for (int q = 0; q < 4; q++)
            *(float4*)(g_xp2f + grow * 32 + c0 + q * 4) = *(float4*)&v[q * 4];
        if ((t & 1) == 0) {
            g_as2[grow] = ps;
            g_ad2[grow] = pd;
        }
    }
}

// ---- layer-2 aggregation: warp/node, fp32 gathers, packed FFMA2, deg reset -
__global__ void __launch_bounds__(256)
k_agg2(const float* __restrict__ b2, float* __restrict__ out) {
    int gw = (blockIdx.x * blockDim.x + threadIdx.x) >> 5;
    int lane = threadIdx.x & 31;
    if (gw >= NN) return;
    int i = gw;
    int deg = g_deg[i]; if (deg > SMAX) deg = SMAX;
    const int* ebase = g_spad + i * SMAX;
    float ad = g_ad2[i];
    int q8 = lane >> 3;       // gather role: edge sub-slot 0..3
    int cg8 = lane & 7;       // gather role: channel group (4 floats)

    // self contribution (implicit self loop)
    float wself = __expf(leaky(g_as2[i] + ad));
    float den = (lane == 0) ? wself : 0.f;
    unsigned long long acc2[2] = {0ull, 0ull};
    if (q8 == 0) {
        unsigned long long wp = pack2(wself);
        ulonglong2 p = *(const ulonglong2*)(g_xp2f + i * 32 + cg8 * 4);
        fma2(acc2[0], wp, p.x);
        fma2(acc2[1], wp, p.y);
    }

    for (int base = 0; base < deg; base += 32) {
        int n = deg - base; if (n > 32) n = 32;
        int src_l = i;
        float w_l = 0.f;
        if (lane < n) {
            src_l = ebase[base + lane];
            w_l = __expf(leaky(g_as2[src_l] + ad));
        }
        den += w_l;
        int niter = (n + 3) >> 2;
        for (int j = 0; j < niter; j++) {
            int slot = 4 * j + q8;
            int src = __shfl_sync(0xffffffffu, src_l, slot);
            float wv = __shfl_sync(0xffffffffu, w_l, slot);
            if (slot < n) {
                unsigned long long wp = pack2(wv);
                ulonglong2 p = *(const ulonglong2*)(g_xp2f + src * 32 + cg8 * 4);
                fma2(acc2[0], wp, p.x);
                fma2(acc2[1], wp, p.y);
            }
        }
    }
    // reset degree for the next replay (deterministic rebuild)
    if (lane == 0) g_deg[i] = 0;

    #pragma unroll
    for (int o = 16; o; o >>= 1)
        den += __shfl_xor_sync(0xffffffffu, den, o);
    // unpack + combine the 4 edge-sub-slot groups (stride 8, 16)
    float a0, a1, a2, a3;
    { float2 u = unpk2(acc2[0]); a0 = u.x; a1 = u.y; }
    { float2 u = unpk2(acc2[1]); a2 = u.x; a3 = u.y; }
    a0 += __shfl_xor_sync(0xffffffffu, a0, 8);
    a1 += __shfl_xor_sync(0xffffffffu, a1, 8);
    a2 += __shfl_xor_sync(0xffffffffu, a2, 8);
    a3 += __shfl_xor_sync(0xffffffffu, a3, 8);
    a0 += __shfl_xor_sync(0xffffffffu, a0, 16);
    a1 += __shfl_xor_sync(0xffffffffu, a1, 16);
    a2 += __shfl_xor_sync(0xffffffffu, a2, 16);
    a3 += __shfl_xor_sync(0xffffffffu, a3, 16);
    float inv = 1.0f / den;
    if (q8 == 0) {
        int ch0 = cg8 * 4;
        float4 bb = *(const float4*)(b2 + ch0);
        float4 o;
        o.x = fmaf(a0, inv, bb.x);
        o.y = fmaf(a1, inv, bb.y);
        o.z = fmaf(a2, inv, bb.z);
        o.w = fmaf(a3, inv, bb.w);
        *(float4*)(out + i * 32 + ch0) = o;
    }
}

// ---------------- launch ----------------------------------------------------
extern "C" void kernel_launch(void* const* d_in, const int* in_sizes, int n_in,
                              void* d_out, int out_size) {
    const float* x   = (const float*)d_in[0];
    const int*   ei  = (const int*)  d_in[1];
    const float* W1  = (const float*)d_in[2];
    const float* as1 = (const float*)d_in[3];
    const float* ad1 = (const float*)d_in[4];
    const float* b1  = (const float*)d_in[5];
    const float* W2  = (const float*)d_in[6];
    const float* as2 = (const float*)d_in[7];
    const float* ad2 = (const float*)d_in[8];
    const float* b2  = (const float*)d_in[9];
    float* out = (float*)d_out;

    const int nblkE4 = (EE / 4 + 255) / 256;
    const int nblkW  = (NN * 32 + 255) / 256;   // one warp per node

    static bool init_done = false;
    static cudaStream_t s2 = 0;
    static cudaEvent_t evF = 0, evJ = 0;
    if (!init_done) {
        cudaFuncSetAttribute(k_gemm1, cudaFuncAttributeMaxDynamicSharedMemorySize,
                             GA_SMEM);
        cudaStream_t st;
        if (cudaStreamCreateWithFlags(&st, cudaStreamNonBlocking) == cudaSuccess &&
            cudaEventCreateWithFlags(&evF, cudaEventDisableTiming) == cudaSuccess &&
            cudaEventCreateWithFlags(&evJ, cudaEventDisableTiming) == cudaSuccess) {
            s2 = st;
        } else {
            s2 = 0;
        }
        init_done = true;
    }

    // fork GEMM1 (independent of adjacency build) onto second stream
    if (s2) {
        cudaEventRecord(evF, 0);
        cudaStreamWaitEvent(s2, evF, 0);
        k_gemm1<<<(NN + 63) / 64, 256, GA_SMEM, s2>>>(x, W1, as1, ad1);
        cudaEventRecord(evJ, s2);
    }

    // adjacency build: single fused kernel (rank+scatter)
    k_bucket<<<nblkE4, 256>>>(ei);

    if (s2) {
        cudaStreamWaitEvent(0, evJ, 0);
    } else {
        k_gemm1<<<(NN + 63) / 64, 256, GA_SMEM>>>(x, W1, as1, ad1);
    }

    k_agg1<<<nblkW, 256>>>(b1);
    k_gemm2<<<(NN + 127) / 128, 256>>>(W2, as2, ad2);
    k_agg2<<<nblkW, 256>>>(b2, out);
}

// round 16
// speedup vs baseline: 1.4615x; 1.0177x over previous
#include <cuda_runtime.h>
#include <cuda_fp16.h>
#include <mma.h>

using namespace nvcuda;

// Problem constants (fixed by the dataset)
#define NN   50000
#define EE   800000
#define D1   128
#define HH   4
#define CC1  32
#define DOUT 32
#define SLOPE 0.2f
#define SMAX 128          // per-node bucket capacity (avg deg 16; overflow ~impossible)

// ---------------- scratch (static device arrays: no allocation) -------------
__device__ int     g_deg[NN];        // zero at load; reset by k_agg2 each run
__device__ int     g_spad[NN * SMAX];// padded per-dst source buckets
__device__ __align__(16) __half2 g_xp1h[NN * 64];
__device__ __align__(16) __half  g_hh[NN * D1];
__device__ __align__(16) float   g_xp2f[NN * DOUT];   // xp2 in fp32
__device__ float   g_as1[NN * HH];
__device__ float   g_ad1[NN * HH];
__device__ float   g_as2[NN];
__device__ float   g_ad2[NN];

__device__ __forceinline__ float leaky(float v) { return v > 0.f ? v : SLOPE * v; }

// packed fp32x2 FMA (Blackwell): d += a*b elementwise on 2 floats
__device__ __forceinline__ void fma2(unsigned long long& d, unsigned long long a,
                                     unsigned long long b) {
    asm("fma.rn.f32x2 %0, %1, %2, %0;" : "+l"(d) : "l"(a), "l"(b));
}
__device__ __forceinline__ unsigned long long pack2(float x) {
    unsigned long long r;
    asm("mov.b64 %0, {%1, %1};" : "=l"(r) : "f"(x));
    return r;
}
__device__ __forceinline__ float2 unpk2(unsigned long long v) {
    float2 r;
    asm("mov.b64 {%0, %1}, %2;" : "=f"(r.x), "=f"(r.y) : "l"(v));
    return r;
}

// ---- fused rank+scatter: ONE kernel builds the whole adjacency -------------
__global__ void k_bucket(const int* __restrict__ ei) {
    int e4 = blockIdx.x * blockDim.x + threadIdx.x;
    if (e4 < EE / 4) {
        int4 s = ((const int4*)ei)[e4];
        int4 d = ((const int4*)(ei + EE))[e4];
        int r;
        r = atomicAdd(&g_deg[d.x], 1); if (r < SMAX) g_spad[d.x * SMAX + r] = s.x;
        r = atomicAdd(&g_deg[d.y], 1); if (r < SMAX) g_spad[d.y * SMAX + r] = s.y;
        r = atomicAdd(&g_deg[d.z], 1); if (r < SMAX) g_spad[d.z * SMAX + r] = s.z;
        r = atomicAdd(&g_deg[d.w], 1); if (r < SMAX) g_spad[d.w * SMAX + r] = s.w;
    }
}

// ---- GEMM1 (tensor cores): xp1 = x @ W1, fp16 in / fp32 acc ---------------
#define GA_LD 136
#define GA_ABYTES (64 * GA_LD * 2)
#define GA_BBYTES (128 * GA_LD * 2)
#define GA_SMEM   (GA_ABYTES + GA_BBYTES)
#define GC_LD 132

__global__ void __launch_bounds__(256)
k_gemm1(const float* __restrict__ x, const float* __restrict__ W,
        const float* __restrict__ asrc, const float* __restrict__ adst) {
    extern __shared__ char smem_raw[];
    __half* Ah = (__half*)smem_raw;
    __half* Bh = (__half*)(smem_raw + GA_ABYTES);
    float*  Cf = (float*)smem_raw;               // reused after mainloop

    int t = threadIdx.x;
    int lane = t & 31;
    int warp = t >> 5;
    int row0 = blockIdx.x * 64;
    int wm = warp >> 2;
    int wn = warp & 3;

    #pragma unroll
    for (int i = 0; i < 8; i++) {
        int idx = t + i * 256;
        int row = idx >> 5;
        int c4 = (idx & 31) * 4;
        int grow = row0 + row;
        float4 v = (grow < NN) ? *(const float4*)(x + grow * 128 + c4)
                               : make_float4(0, 0, 0, 0);
        __half* p = Ah + row * GA_LD + c4;
        p[0] = __float2half_rn(v.x); p[1] = __float2half_rn(v.y);
        p[2] = __float2half_rn(v.z); p[3] = __float2half_rn(v.w);
    }
    #pragma unroll
    for (int i = 0; i < 16; i++) {
        int idx = t + i * 256;
        int row = idx >> 5;
        int c4 = (idx & 31) * 4;
        float4 v = *(const float4*)(W + row * 128 + c4);
        __half* p = Bh + row * GA_LD + c4;
        p[0] = __float2half_rn(v.x); p[1] = __float2half_rn(v.y);
        p[2] = __float2half_rn(v.z); p[3] = __float2half_rn(v.w);
    }
    __syncthreads();

    wmma::fragment<wmma::accumulator, 16, 16, 16, float> c[2][2];
    #pragma unroll
    for (int i = 0; i < 2; i++)
        #pragma unroll
        for (int j = 0; j < 2; j++)
            wmma::fill_fragment(c[i][j], 0.0f);

    #pragma unroll
    for (int k0 = 0; k0 < 128; k0 += 16) {
        wmma::fragment<wmma::matrix_a, 16, 16, 16, __half, wmma::row_major> a[2];
        wmma::fragment<wmma::matrix_b, 16, 16, 16, __half, wmma::row_major> b[2];
        #pragma unroll
        for (int i = 0; i < 2; i++)
            wmma::load_matrix_sync(a[i], Ah + (wm * 32 + i * 16) * GA_LD + k0, GA_LD);
        #pragma unroll
        for (int j = 0; j < 2; j++)
            wmma::load_matrix_sync(b[j], Bh + k0 * GA_LD + wn * 32 + j * 16, GA_LD);
        #pragma unroll
        for (int i = 0; i < 2; i++)
            #pragma unroll
            for (int j = 0; j < 2; j++)
                wmma::mma_sync(c[i][j], a[i], b[j], c[i][j]);
    }
    __syncthreads();

    #pragma unroll
    for (int i = 0; i < 2; i++)
        #pragma unroll
        for (int j = 0; j < 2; j++)
            wmma::store_matrix_sync(Cf + (wm * 32 + i * 16) * GC_LD + wn * 32 + j * 16,
                                    c[i][j], GC_LD, wmma::mem_row_major);
    __syncthreads();

    int c0 = lane * 4;
    float4 asv = *(const float4*)(asrc + c0);
    float4 adv = *(const float4*)(adst + c0);
    int h = lane >> 3;
    #pragma unroll
    for (int rr = 0; rr < 8; rr++) {
        int row = warp * 8 + rr;
        int grow = row0 + row;
        float4 v = *(const float4*)(Cf + row * GC_LD + c0);
        if (grow < NN) {
            __half2 h0 = __floats2half2_rn(v.x, v.y);
            __half2 h1 = __floats2half2_rn(v.z, v.w);
            uint2 pk;
            pk.x = *(unsigned*)&h0;
            pk.y = *(unsigned*)&h1;
            *(uint2*)(g_xp1h + grow * 64 + lane * 2) = pk;
        }
        float ps = v.x * asv.x + v.y * asv.y + v.z * asv.z + v.w * asv.w;
        float pd = v.x * adv.x + v.y * adv.y + v.z * adv.z + v.w * adv.w;
        #pragma unroll
        for (int o = 1; o < 8; o <<= 1) {
            ps += __shfl_xor_sync(0xffffffffu, ps, o);
            pd += __shfl_xor_sync(0xffffffffu, pd, o);
        }
        if ((lane & 7) == 0 && grow < NN) {
            g_as1[grow * 4 + h] = ps;
            g_ad1[grow * 4 + h] = pd;
        }
    }
}

// ---- layer-1 aggregation: warp/node, fp16 gathers, plain FMA (champion) ----
__global__ void __launch_bounds__(256) k_agg1(const float* __restrict__ b1) {
    int gw = (blockIdx.x * blockDim.x + threadIdx.x) >> 5;
    int lane = threadIdx.x & 31;
    if (gw >= NN) return;
    int i = gw;
    int deg = g_deg[i]; if (deg > SMAX) deg = SMAX;
    const int* ebase = g_spad + i * SMAX;
    int myhead = lane >> 3;          // weight-compute role: head
    int es = lane & 7;               // weight-compute role: edge slot
    int h4 = lane >> 4;              // gather role: edge parity
    int lane15 = lane & 15;          // gather role: channel group (8 ch)
    int wbase = (lane & 12) << 1;    // lane base holding my gather-head's weights
    float adh = g_ad1[i * 4 + myhead];

    // self contribution (implicit self loop)
    float denl = (es == 0) ? __expf(leaky(g_as1[i * 4 + myhead] + adh)) : 0.f;
    float acc[8];
    #pragma unroll
    for (int k = 0; k < 8; k++) acc[k] = 0.f;
    if (h4 == 0) {
        int hh2 = lane15 >> 2;       // head covering my channel group
        float wself = __expf(leaky(g_as1[i * 4 + hh2] + g_ad1[i * 4 + hh2]));
        uint4 p = *(const uint4*)(g_xp1h + i * 64 + lane15 * 4);
        float2 v0 = __half22float2(*(__half2*)&p.x);
        float2 v1 = __half22float2(*(__half2*)&p.y);
        float2 v2 = __half22float2(*(__half2*)&p.z);
        float2 v3 = __half22float2(*(__half2*)&p.w);
        acc[0] = wself * v0.x; acc[1] = wself * v0.y;
        acc[2] = wself * v1.x; acc[3] = wself * v1.y;
        acc[4] = wself * v2.x; acc[5] = wself * v2.y;
        acc[6] = wself * v3.x; acc[7] = wself * v3.y;
    }

    for (int base = 0; base < deg; base += 8) {
        int n = deg - base; if (n > 8) n = 8;
        int src_l = i;
        float w_l = 0.f;
        if (es < n) {
            src_l = ebase[base + es];
            w_l = __expf(leaky(g_as1[src_l * 4 + myhead] + adh));
        }
        denl += w_l;
        int npair = (n + 1) >> 1;
        for (int j = 0; j < npair; j++) {
            int slot = 2 * j + h4;
            int src = __shfl_sync(0xffffffffu, src_l, slot);
            float wv = __shfl_sync(0xffffffffu, w_l, wbase + slot);
            if (slot < n) {
                uint4 p = *(const uint4*)(g_xp1h + src * 64 + lane15 * 4);
                float2 v0 = __half22float2(*(__half2*)&p.x);
                float2 v1 = __half22float2(*(__half2*)&p.y);
                float2 v2 = __half22float2(*(__half2*)&p.z);
                float2 v3 = __half22float2(*(__half2*)&p.w);
                acc[0] = fmaf(wv, v0.x, acc[0]); acc[1] = fmaf(wv, v0.y, acc[1]);
                acc[2] = fmaf(wv, v1.x, acc[2]); acc[3] = fmaf(wv, v1.y, acc[3]);
                acc[4] = fmaf(wv, v2.x, acc[4]); acc[5] = fmaf(wv, v2.y, acc[5]);
                acc[6] = fmaf(wv, v3.x, acc[6]); acc[7] = fmaf(wv, v3.y, acc[7]);
            }
        }
    }
    // per-head denominators (8-lane groups), broadcast to gather lanes
    denl += __shfl_xor_sync(0xffffffffu, denl, 1);
    denl += __shfl_xor_sync(0xffffffffu, denl, 2);
    denl += __shfl_xor_sync(0xffffffffu, denl, 4);
    float denv = __shfl_sync(0xffffffffu, denl, wbase);
    float inv = 1.0f / denv;
    // combine the two edge-parity halves
    #pragma unroll
    for (int k = 0; k < 8; k++)
        acc[k] += __shfl_xor_sync(0xffffffffu, acc[k], 16);
    // bias + relu + fp16 store (lanes 0-15 cover all 128 channels)
    int ch0 = lane15 * 8;
    float4 bb0 = *(const float4*)(b1 + ch0);
    float4 bb1 = *(const float4*)(b1 + ch0 + 4);
    __half hv[8];
    hv[0] = __float2half_rn(fmaxf(fmaf(acc[0], inv, bb0.x), 0.f));
    hv[1] = __float2half_rn(fmaxf(fmaf(acc[1], inv, bb0.y), 0.f));
    hv[2] = __float2half_rn(fmaxf(fmaf(acc[2], inv, bb0.z), 0.f));
    hv[3] = __float2half_rn(fmaxf(fmaf(acc[3], inv, bb0.w), 0.f));
    hv[4] = __float2half_rn(fmaxf(fmaf(acc[4], inv, bb1.x), 0.f));
    hv[5] = __float2half_rn(fmaxf(fmaf(acc[5], inv, bb1.y), 0.f));
    hv[6] = __float2half_rn(fmaxf(fmaf(acc[6], inv, bb1.z), 0.f));
    hv[7] = __float2half_rn(fmaxf(fmaf(acc[7], inv, bb1.w), 0.f));
    if (h4 == 0)
        *(uint4*)(g_hh + i * 128 + ch0) = *(uint4*)hv;
}

// ---- GEMM2 (tensor cores): xp2 = h @ W2 (fp32 out) + fused attention dots --
#define G2_ALD 136
#define G2_BLD 40
#define G2_CLD 36

__global__ void __launch_bounds__(256)
k_gemm2(const float* __restrict__ W2,
        const float* __restrict__ asrc, const float* __restrict__ adst) {
    __shared__ __half Ah[128 * G2_ALD];
    __shared__ __half Bh[128 * G2_BLD];
    float* Cf = (float*)Ah;

    int t = threadIdx.x;
    int warp = t >> 5;
    int row0 = blockIdx.x * 128;

    #pragma unroll
    for (int i = 0; i < 8; i++) {
        int idx = t + i * 256;
        int row = idx >> 4;
        int q = idx & 15;
        int grow = row0 + row;
        uint4 v = (grow < NN) ? *(const uint4*)(g_hh + grow * 128 + q * 8)
                              : make_uint4(0, 0, 0, 0);
        *(uint4*)(Ah + row * G2_ALD + q * 8) = v;
    }
    #pragma unroll
    for (int i = 0; i < 4; i++) {
        int idx = t + i * 256;
        int row = idx >> 3;
        int c4 = (idx & 7) * 4;
        float4 v = *(const float4*)(W2 + row * 32 + c4);
        __half* p = Bh + row * G2_BLD + c4;
        p[0] = __float2half_rn(v.x); p[1] = __float2half_rn(v.y);
        p[2] = __float2half_rn(v.z); p[3] = __float2half_rn(v.w);
    }
    __syncthreads();

    wmma::fragment<wmma::accumulator, 16, 16, 16, float> c[2];
    wmma::fill_fragment(c[0], 0.0f);
    wmma::fill_fragment(c[1], 0.0f);

    #pragma unroll
    for (int k0 = 0; k0 < 128; k0 += 16) {
        wmma::fragment<wmma::matrix_a, 16, 16, 16, __half, wmma::row_major> a;
        wmma::fragment<wmma::matrix_b, 16, 16, 16, __half, wmma::row_major> b[2];
        wmma::load_matrix_sync(a, Ah + (warp * 16) * G2_ALD + k0, G2_ALD);
        wmma::load_matrix_sync(b[0], Bh + k0 * G2_BLD + 0, G2_BLD);
        wmma::load_matrix_sync(b[1], Bh + k0 * G2_BLD + 16, G2_BLD);
        wmma::mma_sync(c[0], a, b[0], c[0]);
        wmma::mma_sync(c[1], a, b[1], c[1]);
    }
    __syncthreads();

    wmma::store_matrix_sync(Cf + (warp * 16) * G2_CLD + 0,  c[0], G2_CLD,
                            wmma::mem_row_major);
    wmma::store_matrix_sync(Cf + (warp * 16) * G2_CLD + 16, c[1], G2_CLD,
                            wmma::mem_row_major);
    __syncthreads();

    int row = t >> 1;
    int c0 = (t & 1) * 16;
    int grow = row0 + row;
    float v[16];
    #pragma unroll
    for (int j = 0; j < 16; j++) v[j] = Cf[row * G2_CLD + c0 + j];

    float ps = 0.f, pd = 0.f;
    #pragma unroll
    for (int j = 0; j < 16; j++) {
        ps = fmaf(v[j], asrc[c0 + j], ps);
        pd = fmaf(v[j], adst[c0 + j], pd);
    }
    ps += __shfl_xor_sync(0xffffffffu, ps, 1);
    pd += __shfl_xor_sync(0xffffffffu, pd, 1);

    if (grow < NN) {
        #pragma unroll
        for (int q = 0; q < 4; q++)
            *(float4*)(g_xp2f + grow * 32 + c0 + q * 4) = *(float4*)&v[q * 4];
        if ((t & 1) == 0) {
            g_as2[grow] = ps;
            g_ad2[grow] = pd;
        }
    }
}

// ---- layer-2 aggregation: warp/node, fp32 gathers, packed FFMA2, deg reset -
__global__ void __launch_bounds__(256)
k_agg2(const float* __restrict__ b2, float* __restrict__ out) {
    int gw = (blockIdx.x * blockDim.x + threadIdx.x) >> 5;
    int lane = threadIdx.x & 31;
    if (gw >= NN) return;
    int i = gw;
    int deg = g_deg[i]; if (deg > SMAX) deg = SMAX;
    const int* ebase = g_spad + i * SMAX;
    float ad = g_ad2[i];
    int q8 = lane >> 3;       // gather role: edge sub-slot 0..3
    int cg8 = lane & 7;       // gather role: channel group (4 floats)

    // self contribution (implicit self loop)
    float wself = __expf(leaky(g_as2[i] + ad));
    float den = (lane == 0) ? wself : 0.f;
    unsigned long long acc2[2] = {0ull, 0ull};
    if (q8 == 0) {
        unsigned long long wp = pack2(wself);
        ulonglong2 p = *(const ulonglong2*)(g_xp2f + i * 32 + cg8 * 4);
        fma2(acc2[0], wp, p.x);
        fma2(acc2[1], wp, p.y);
    }

    for (int base = 0; base < deg; base += 32) {
        int n = deg - base; if (n > 32) n = 32;
        int src_l = i;
        float w_l = 0.f;
        if (lane < n) {
            src_l = ebase[base + lane];
            w_l = __expf(leaky(g_as2[src_l] + ad));
        }
        den += w_l;
        int niter = (n + 3) >> 2;
        for (int j = 0; j < niter; j++) {
            int slot = 4 * j + q8;
            int src = __shfl_sync(0xffffffffu, src_l, slot);
            float wv = __shfl_sync(0xffffffffu, w_l, slot);
            if (slot < n) {
                unsigned long long wp = pack2(wv);
                ulonglong2 p = *(const ulonglong2*)(g_xp2f + src * 32 + cg8 * 4);
                fma2(acc2[0], wp, p.x);
                fma2(acc2[1], wp, p.y);
            }
        }
    }
    // reset degree for the next replay (deterministic rebuild)
    if (lane == 0) g_deg[i] = 0;

    #pragma unroll
    for (int o = 16; o; o >>= 1)
        den += __shfl_xor_sync(0xffffffffu, den, o);
    // unpack + combine the 4 edge-sub-slot groups (stride 8, 16)
    float a0, a1, a2, a3;
    { float2 u = unpk2(acc2[0]); a0 = u.x; a1 = u.y; }
    { float2 u = unpk2(acc2[1]); a2 = u.x; a3 = u.y; }
    a0 += __shfl_xor_sync(0xffffffffu, a0, 8);
    a1 += __shfl_xor_sync(0xffffffffu, a1, 8);
    a2 += __shfl_xor_sync(0xffffffffu, a2, 8);
    a3 += __shfl_xor_sync(0xffffffffu, a3, 8);
    a0 += __shfl_xor_sync(0xffffffffu, a0, 16);
    a1 += __shfl_xor_sync(0xffffffffu, a1, 16);
    a2 += __shfl_xor_sync(0xffffffffu, a2, 16);
    a3 += __shfl_xor_sync(0xffffffffu, a3, 16);
    float inv = 1.0f / den;
    if (q8 == 0) {
        int ch0 = cg8 * 4;
        float4 bb = *(const float4*)(b2 + ch0);
        float4 o;
        o.x = fmaf(a0, inv, bb.x);
        o.y = fmaf(a1, inv, bb.y);
        o.z = fmaf(a2, inv, bb.z);
        o.w = fmaf(a3, inv, bb.w);
        *(float4*)(out + i * 32 + ch0) = o;
    }
}

// ---------------- launch ----------------------------------------------------
extern "C" void kernel_launch(void* const* d_in, const int* in_sizes, int n_in,
                              void* d_out, int out_size) {
    const float* x   = (const float*)d_in[0];
    const int*   ei  = (const int*)  d_in[1];
    const float* W1  = (const float*)d_in[2];
    const float* as1 = (const float*)d_in[3];
    const float* ad1 = (const float*)d_in[4];
    const float* b1  = (const float*)d_in[5];
    const float* W2  = (const float*)d_in[6];
    const float* as2 = (const float*)d_in[7];
    const float* ad2 = (const float*)d_in[8];
    const float* b2  = (const float*)d_in[9];
    float* out = (float*)d_out;

    const int nblkE4 = (EE / 4 + 255) / 256;
    const int nblkW  = (NN * 32 + 255) / 256;   // one warp per node

    static bool init_done = false;
    static cudaStream_t s2 = 0;
    static cudaEvent_t evF = 0, evJ = 0;
    if (!init_done) {
        cudaFuncSetAttribute(k_gemm1, cudaFuncAttributeMaxDynamicSharedMemorySize,
                             GA_SMEM);
        cudaStream_t st;
        if (cudaStreamCreateWithFlags(&st, cudaStreamNonBlocking) == cudaSuccess &&
            cudaEventCreateWithFlags(&evF, cudaEventDisableTiming) == cudaSuccess &&
            cudaEventCreateWithFlags(&evJ, cudaEventDisableTiming) == cudaSuccess) {
            s2 = st;
        } else {
            s2 = 0;
        }
        init_done = true;
    }

    // fork GEMM1 (independent of adjacency build) onto second stream
    if (s2) {
        cudaEventRecord(evF, 0);
        cudaStreamWaitEvent(s2, evF, 0);
        k_gemm1<<<(NN + 63) / 64, 256, GA_SMEM, s2>>>(x, W1, as1, ad1);
        cudaEventRecord(evJ, s2);
    }

    // adjacency build: single fused kernel (rank+scatter)
    k_bucket<<<nblkE4, 256>>>(ei);

    if (s2) {
        cudaStreamWaitEvent(0, evJ, 0);
    } else {
        k_gemm1<<<(NN + 63) / 64, 256, GA_SMEM>>>(x, W1, as1, ad1);
    }

    k_agg1<<<nblkW, 256>>>(b1);
    k_gemm2<<<(NN + 127) / 128, 256>>>(W2, as2, ad2);
    k_agg2<<<nblkW, 256>>>(b2, out);
}